// round 7
// baseline (speedup 1.0000x reference)
#include <cuda_runtime.h>
#include <cuda_bf16.h>
#include <cstdint>

// DepthToSpace: x [8, 64, 256, 256] fp32 -> out [8, 4, 1024, 1024] fp32
// out[b, s, 4h+r, 4w+c] = x[b, 16s+4r+c, h, w]
//
// R6: R5 structure + evict-first (.cs) input loads.
// Measured: effective 7.4 TB/s vs 5.9 TB/s DRAM => L2 (126MB) elides part of
// the output writeback across graph replays (dirty lines overwritten before
// eviction). Input lines are single-use; caching them only evicts dirty
// output. Streaming the input (__ldcs) maximizes output retention in L2 and
// cuts steady-state DRAM write traffic.
//
//   - stores: consecutive lanes -> consecutive float4  => coalesced STG.128
//   - loads:  consecutive lanes -> consecutive 4B per channel => 128B wavefronts

__global__ __launch_bounds__(256, 8)
void depth_to_space_kernel(const float* __restrict__ x,
                           float4* __restrict__ out4)
{
    const unsigned t    = blockIdx.x * blockDim.x + threadIdx.x;  // 0 .. 4194303
    const unsigned lane = t & 31;
    const unsigned wid  = t >> 5;                                 // 0 .. 131071

    // This warp covers output-float4 indices [wid*64, wid*64+64).
    const unsigned ofi_base = wid * 64;
    const unsigned orow = (ofi_base >> 8) & 1023;   // output row within (b,s)
    const unsigned bs   =  ofi_base >> 18;          // b*4 + s, 0..31

    const unsigned h   = orow >> 2;                 // input spatial row
    const unsigned r   = orow & 3;                  // intra-cell row
    const unsigned ch0 = bs * 16 + r * 4;           // first of 4 input channels

    const unsigned w0   = (ofi_base & 255) + lane;       // col for k=0
    const unsigned in_a = (ch0 << 16) + (h << 8) + w0;   // scalar index, < 2^24
    const unsigned CH   = 1u << 16;                      // channel stride (floats)

    float v[2][4];
    #pragma unroll
    for (int k = 0; k < 2; k++) {
        const float* a = x + in_a + 32u * k;
        #pragma unroll
        for (int c = 0; c < 4; c++)
            v[k][c] = __ldcs(a + c * CH);   // evict-first: single-use stream
    }

    const unsigned ob = ofi_base + lane;
    #pragma unroll
    for (int k = 0; k < 2; k++)
        out4[ob + 32u * k] = make_float4(v[k][0], v[k][1], v[k][2], v[k][3]);
}

extern "C" void kernel_launch(void* const* d_in, const int* in_sizes, int n_in,
                              void* d_out, int out_size)
{
    const float* x  = (const float*)d_in[0];
    float4*      o4 = (float4*)d_out;

    const int threads = 256;
    const int blocks  = 16384;   // 4,194,304 threads, 2 float4 each
    depth_to_space_kernel<<<blocks, threads>>>(x, o4);
}